// round 1
// baseline (speedup 1.0000x reference)
#include <cuda_runtime.h>
#include <math.h>

// Problem constants
#define BB 32
#define SS 2048
#define EE 1024
#define HH 1024
#define NHT 8          // number of h-tiles in main GEMM (HH / BN)

// Scratch (allocation-free rule: __device__ globals)
__device__ float g_wq[BB * HH];            // 128 KB
__device__ float g_partial[BB * SS * NHT]; // 2 MB : per-h-tile score partials
__device__ float g_alpha[BB * SS];         // 256 KB
__device__ float g_t[BB * EE];             // 128 KB : enc^T @ alpha

// ---------------------------------------------------------------------------
// Kernel A: wq[b,h] = dot(dec[b,:], W_q[h,:])   (warp per (b,h))
// grid (HH/8, BB), block 256 (8 warps)
// ---------------------------------------------------------------------------
__global__ void wq_kernel(const float* __restrict__ dec,
                          const float* __restrict__ Wq) {
    int warp = threadIdx.x >> 5;
    int lane = threadIdx.x & 31;
    int h = blockIdx.x * 8 + warp;
    int b = blockIdx.y;
    const float* wrow = Wq + (size_t)h * EE;
    const float* drow = dec + (size_t)b * EE;
    float acc = 0.f;
#pragma unroll 8
    for (int e = lane; e < EE; e += 32)
        acc = fmaf(wrow[e], drow[e], acc);
#pragma unroll
    for (int off = 16; off > 0; off >>= 1)
        acc += __shfl_xor_sync(0xFFFFFFFF, acc, off);
    if (lane == 0) g_wq[b * HH + h] = acc;
}

// ---------------------------------------------------------------------------
// Kernel B: fused GEMM + score-partial epilogue.
// ctx[s,h] = sum_e enc[b,s,e] * Wk[h,e]   (NT gemm, both K-major)
// partial[b,s,ht] = sum_{h in tile} V[h] * tanh(ctx[s,h] + wq[b,h])
// Tile 128x128x16, 256 threads, 8x8 per thread.
// grid (HH/128=8, SS/128=16, BB=32)
// ---------------------------------------------------------------------------
#define BM 128
#define BN 128
#define BKK 16

__global__ __launch_bounds__(256, 2)
void gemm_score_kernel(const float* __restrict__ enc,
                       const float* __restrict__ Wk,
                       const float* __restrict__ V) {
    __shared__ float As[BKK][BM];
    __shared__ float Bs[BKK][BN];
    __shared__ float wqs[BN];
    __shared__ float vs[BN];
    __shared__ float red[BM][17];   // padded to dodge bank conflicts

    const int tid = threadIdx.x;
    const int ht  = blockIdx.x;
    const int st  = blockIdx.y;
    const int b   = blockIdx.z;
    const int tx  = tid & 15;       // h direction (8 cols each)
    const int ty  = tid >> 4;       // s direction (8 rows each)

    const float* Abase = enc + (size_t)b * SS * EE + (size_t)(st * BM) * EE;
    const float* Bbase = Wk + (size_t)(ht * BN) * EE;

    if (tid < BN) {
        wqs[tid] = g_wq[b * HH + ht * BN + tid];
        vs[tid]  = V[ht * BN + tid];
    }

    float acc[8][8];
#pragma unroll
    for (int i = 0; i < 8; i++)
#pragma unroll
        for (int j = 0; j < 8; j++) acc[i][j] = 0.f;

    // load mapping: 128 rows x 16 cols = 512 float4; 256 threads x 2
    const int lrow = tid >> 2;          // 0..63
    const int lc4  = (tid & 3) * 4;     // 0,4,8,12

    for (int ko = 0; ko < EE; ko += BKK) {
#pragma unroll
        for (int r = 0; r < 2; r++) {
            int row = lrow + r * 64;
            float4 a = *(const float4*)(Abase + (size_t)row * EE + ko + lc4);
            As[lc4 + 0][row] = a.x;
            As[lc4 + 1][row] = a.y;
            As[lc4 + 2][row] = a.z;
            As[lc4 + 3][row] = a.w;
            float4 bv = *(const float4*)(Bbase + (size_t)row * EE + ko + lc4);
            Bs[lc4 + 0][row] = bv.x;
            Bs[lc4 + 1][row] = bv.y;
            Bs[lc4 + 2][row] = bv.z;
            Bs[lc4 + 3][row] = bv.w;
        }
        __syncthreads();

#pragma unroll
        for (int k = 0; k < BKK; k++) {
            float ar[8], br[8];
            float4 a0 = *(const float4*)&As[k][ty * 8];
            float4 a1 = *(const float4*)&As[k][ty * 8 + 4];
            ar[0]=a0.x; ar[1]=a0.y; ar[2]=a0.z; ar[3]=a0.w;
            ar[4]=a1.x; ar[5]=a1.y; ar[6]=a1.z; ar[7]=a1.w;
            float4 b0 = *(const float4*)&Bs[k][tx * 8];
            float4 b1 = *(const float4*)&Bs[k][tx * 8 + 4];
            br[0]=b0.x; br[1]=b0.y; br[2]=b0.z; br[3]=b0.w;
            br[4]=b1.x; br[5]=b1.y; br[6]=b1.z; br[7]=b1.w;
#pragma unroll
            for (int i = 0; i < 8; i++)
#pragma unroll
                for (int j = 0; j < 8; j++)
                    acc[i][j] = fmaf(ar[i], br[j], acc[i][j]);
        }
        __syncthreads();
    }

    // Epilogue: ssum[i] = sum_j V[h_j] * tanh(acc + wq[h_j]) for this thread's 8 h's
    float ssum[8];
#pragma unroll
    for (int i = 0; i < 8; i++) {
        float s = 0.f;
#pragma unroll
        for (int j = 0; j < 8; j++) {
            int hc = tx * 8 + j;
            s = fmaf(vs[hc], tanhf(acc[i][j] + wqs[hc]), s);
        }
        ssum[i] = s;
    }
#pragma unroll
    for (int i = 0; i < 8; i++) red[ty * 8 + i][tx] = ssum[i];
    __syncthreads();

    if (tid < BM) {
        float r = 0.f;
#pragma unroll
        for (int t = 0; t < 16; t++) r += red[tid][t];
        int s = st * BM + tid;
        g_partial[(size_t)(b * SS + s) * NHT + ht] = r;   // deterministic: unique slot
    }
}

// ---------------------------------------------------------------------------
// Kernel C: reduce partials -> score (output), softmax -> g_alpha.
// grid BB, block 256; each thread owns 8 s-positions.
// ---------------------------------------------------------------------------
__global__ void softmax_kernel(float* __restrict__ out_score) {
    __shared__ float sred[256];
    const int b = blockIdx.x;
    const int tid = threadIdx.x;

    float sc[8];
    float mx = -1e30f;
#pragma unroll
    for (int i = 0; i < 8; i++) {
        int s = i * 256 + tid;
        const float* p = g_partial + (size_t)(b * SS + s) * NHT;
        float v = 0.f;
#pragma unroll
        for (int t = 0; t < NHT; t++) v += p[t];
        sc[i] = v;
        out_score[b * SS + s] = v;
        mx = fmaxf(mx, v);
    }
    sred[tid] = mx; __syncthreads();
    for (int off = 128; off > 0; off >>= 1) {
        if (tid < off) sred[tid] = fmaxf(sred[tid], sred[tid + off]);
        __syncthreads();
    }
    mx = sred[0]; __syncthreads();

    float ex[8];
    float sum = 0.f;
#pragma unroll
    for (int i = 0; i < 8; i++) { ex[i] = expf(sc[i] - mx); sum += ex[i]; }
    sred[tid] = sum; __syncthreads();
    for (int off = 128; off > 0; off >>= 1) {
        if (tid < off) sred[tid] += sred[tid + off];
        __syncthreads();
    }
    float inv = 1.f / sred[0];
#pragma unroll
    for (int i = 0; i < 8; i++) g_alpha[b * SS + i * 256 + tid] = ex[i] * inv;
}

// ---------------------------------------------------------------------------
// Kernel D: t[b,e] = sum_s enc[b,s,e] * alpha[b,s]   (streaming 256 MB read)
// grid (EE/256, BB), block 256.
// ---------------------------------------------------------------------------
__global__ void context_t_kernel(const float* __restrict__ enc) {
    __shared__ float sa[SS];
    const int b = blockIdx.y;
    const int tid = threadIdx.x;
#pragma unroll
    for (int i = 0; i < SS / 256; i++) sa[i * 256 + tid] = g_alpha[b * SS + i * 256 + tid];
    __syncthreads();

    const int e = blockIdx.x * 256 + tid;
    const float* p = enc + (size_t)b * SS * EE + e;
    float acc = 0.f;
#pragma unroll 8
    for (int s = 0; s < SS; s++)
        acc = fmaf(p[(size_t)s * EE], sa[s], acc);
    g_t[b * EE + e] = acc;
}

// ---------------------------------------------------------------------------
// Kernel E: hidden[b,h] = sum_e Wk[h,e] * t[b,e]    (warp per (b,h))
// grid (HH/8, BB), block 256.
// ---------------------------------------------------------------------------
__global__ void hidden_kernel(const float* __restrict__ Wk,
                              float* __restrict__ out_hidden) {
    int warp = threadIdx.x >> 5;
    int lane = threadIdx.x & 31;
    int h = blockIdx.x * 8 + warp;
    int b = blockIdx.y;
    const float* wrow = Wk + (size_t)h * EE;
    const float* trow = g_t + b * EE;
    float acc = 0.f;
#pragma unroll 8
    for (int e = lane; e < EE; e += 32)
        acc = fmaf(wrow[e], trow[e], acc);
#pragma unroll
    for (int off = 16; off > 0; off >>= 1)
        acc += __shfl_xor_sync(0xFFFFFFFF, acc, off);
    if (lane == 0) out_hidden[b * HH + h] = acc;
}

// ---------------------------------------------------------------------------
extern "C" void kernel_launch(void* const* d_in, const int* in_sizes, int n_in,
                              void* d_out, int out_size) {
    const float* enc = (const float*)d_in[0];   // [B,S,E]
    const float* dec = (const float*)d_in[1];   // [B,E]
    const float* Wk  = (const float*)d_in[2];   // [H,E]
    const float* Wq  = (const float*)d_in[3];   // [H,E]
    const float* V   = (const float*)d_in[4];   // [H]

    float* out_hidden = (float*)d_out;                 // [B,H]
    float* out_score  = (float*)d_out + BB * HH;       // [B,S]

    wq_kernel<<<dim3(HH / 8, BB), 256>>>(dec, Wq);
    gemm_score_kernel<<<dim3(HH / BN, SS / BM, BB), 256>>>(enc, Wk, V);
    softmax_kernel<<<BB, 256>>>(out_score);
    context_t_kernel<<<dim3(EE / 256, BB), 256>>>(enc);
    hidden_kernel<<<dim3(HH / 8, BB), 256>>>(Wk, out_hidden);
}

// round 5
// speedup vs baseline: 2.5685x; 2.5685x over previous
#include <cuda_runtime.h>
#include <math.h>
#include <stdint.h>

// Problem constants
#define BB 32
#define SS 2048
#define EE 1024
#define HH 1024
#define NHT 8            // h-tiles (HH/128)
#define BK 32            // K per staged chunk
#define NCHUNK (EE / BK) // 32
#define A_BYTES (128 * BK * 4)       // 16384
#define STAGE_BYTES (2 * A_BYTES)    // 32768
#define DYN_SMEM (3 * STAGE_BYTES)   // 98304

// Scratch (__device__ globals per allocation rules)
__device__ float g_wq[BB * HH];
__device__ float g_partial[BB * SS * NHT];
__device__ float g_alpha[BB * SS];
__device__ float g_t[BB * EE];
__device__ float g_tpart[8 * BB * EE];

// ---------------------------------------------------------------------------
// helpers
// ---------------------------------------------------------------------------
__device__ __forceinline__ uint32_t smem_u32(const void* p) {
    uint32_t a;
    asm("{ .reg .u64 t; cvta.to.shared.u64 t, %1; cvt.u32.u64 %0, t; }" : "=r"(a) : "l"(p));
    return a;
}
__device__ __forceinline__ void cp16(uint32_t dst, const void* src) {
    asm volatile("cp.async.cg.shared.global [%0], [%1], 16;" :: "r"(dst), "l"(src));
}
#define CP_COMMIT() asm volatile("cp.async.commit_group;" ::: "memory")
#define CP_WAIT1()  asm volatile("cp.async.wait_group 1;" ::: "memory")

// split fp32 pair (a0 = even k, a1 = odd k) into bf16x2 hi + bf16x2 lo residual
__device__ __forceinline__ void split_bf(float a0, float a1,
                                         uint32_t& hi, uint32_t& lo) {
    uint32_t h;
    asm("cvt.rn.bf16x2.f32 %0, %1, %2;" : "=r"(h) : "f"(a1), "f"(a0));
    float h0 = __uint_as_float(h << 16);
    float h1 = __uint_as_float(h & 0xFFFF0000u);
    uint32_t l;
    asm("cvt.rn.bf16x2.f32 %0, %1, %2;" : "=r"(l) : "f"(a1 - h1), "f"(a0 - h0));
    hi = h; lo = l;
}

__device__ __forceinline__ void mma_bf16(float* c, const uint32_t* a, const uint32_t* b) {
    asm volatile(
        "mma.sync.aligned.m16n8k16.row.col.f32.bf16.bf16.f32 "
        "{%0,%1,%2,%3}, {%4,%5,%6,%7}, {%8,%9}, {%0,%1,%2,%3};"
        : "+f"(c[0]), "+f"(c[1]), "+f"(c[2]), "+f"(c[3])
        : "r"(a[0]), "r"(a[1]), "r"(a[2]), "r"(a[3]), "r"(b[0]), "r"(b[1]));
}

// ---------------------------------------------------------------------------
// Kernel A: wq[b,h] = dot(dec[b,:], W_q[h,:])
// ---------------------------------------------------------------------------
__global__ void wq_kernel(const float* __restrict__ dec,
                          const float* __restrict__ Wq) {
    int warp = threadIdx.x >> 5;
    int lane = threadIdx.x & 31;
    int h = blockIdx.x * 8 + warp;
    int b = blockIdx.y;
    const float* wrow = Wq + (size_t)h * EE;
    const float* drow = dec + (size_t)b * EE;
    float acc = 0.f;
#pragma unroll 8
    for (int e = lane; e < EE; e += 32)
        acc = fmaf(wrow[e], drow[e], acc);
#pragma unroll
    for (int off = 16; off > 0; off >>= 1)
        acc += __shfl_xor_sync(0xFFFFFFFF, acc, off);
    if (lane == 0) g_wq[b * HH + h] = acc;
}

// ---------------------------------------------------------------------------
// Kernel B: split-bf16 3-pass mma.sync GEMM 128x128x1024 + fused score epilogue.
// ctx = hi_a*hi_b + hi_a*lo_b + lo_a*hi_b   (fp32 accum, error ~4e-6)
// grid (8, 16, 32), 256 threads (8 warps: 2(M) x 4(N), warp tile 64x32).
// SMEM fp32 stage: elem(m,k) at m*32 + ((k>>2)^(m&7))*4 + (k&3)
// ---------------------------------------------------------------------------
__global__ __launch_bounds__(256, 2)
void gemm_tc_kernel(const float* __restrict__ enc,
                    const float* __restrict__ Wk,
                    const float* __restrict__ V) {
    extern __shared__ float smem[];
    __shared__ float wqs[128];
    __shared__ float vs[128];
    __shared__ float red[128][4];

    const int tid = threadIdx.x;
    const int lane = tid & 31;
    const int wid = tid >> 5;
    const int ht = blockIdx.x;
    const int st = blockIdx.y;
    const int b  = blockIdx.z;
    const int g = lane >> 2;   // 0..7
    const int t = lane & 3;    // 0..3
    const int wm = wid & 1;    // M warp row
    const int wn = wid >> 1;   // N warp col

    if (tid < 128) {
        wqs[tid] = g_wq[b * HH + ht * 128 + tid];
        vs[tid]  = V[ht * 128 + tid];
    }

    const uint32_t sbase = smem_u32(smem);
    const float* Ag = enc + (size_t)b * SS * EE + (size_t)(st * 128) * EE;
    const float* Bg = Wk + (size_t)(ht * 128) * EE;

    auto issue = [&](int stage, int chunk) {
        uint32_t sa = sbase + stage * STAGE_BYTES;
        uint32_t sb = sa + A_BYTES;
        int ko = chunk * BK;
#pragma unroll
        for (int i = 0; i < 4; i++) {
            int idx = i * 256 + tid;
            int m = idx >> 3, kg = idx & 7;
            cp16(sa + m * 128 + ((kg ^ (m & 7)) << 4), Ag + (size_t)m * EE + ko + kg * 4);
        }
#pragma unroll
        for (int i = 0; i < 4; i++) {
            int idx = i * 256 + tid;
            int n = idx >> 3, kg = idx & 7;
            cp16(sb + n * 128 + ((kg ^ (n & 7)) << 4), Bg + (size_t)n * EE + ko + kg * 4);
        }
        CP_COMMIT();
    };

    float c[4][4][4];
#pragma unroll
    for (int mt = 0; mt < 4; mt++)
#pragma unroll
        for (int nt = 0; nt < 4; nt++)
#pragma unroll
            for (int j = 0; j < 4; j++) c[mt][nt][j] = 0.f;

    issue(0, 0);
    issue(1, 1);

    const int t2 = 2 * (t & 1);   // k&3 part of even-k element of the pair

    for (int i = 0; i < NCHUNK; i++) {
        CP_WAIT1();
        __syncthreads();
        if (i + 2 < NCHUNK) issue((i + 2) % 3, i + 2);
        else CP_COMMIT();

        const float* As = smem + (i % 3) * (STAGE_BYTES / 4);
        const float* Bs = As + (A_BYTES / 4);

#pragma unroll
        for (int kk2 = 0; kk2 < 2; kk2++) {          // two k16 steps per BK=32
            const int kgA = kk2 * 4 + (t >> 1);      // k group of k = kbase+2t
            const int kgB = kgA + 2;                 // k group of k+8

            // B fragments: bh/bl [nt][2]
            uint32_t bh[4][2], bl[4][2];
#pragma unroll
            for (int nt = 0; nt < 4; nt++) {
                int n0 = wn * 32 + nt * 8 + g;       // n0 & 7 == g
                const float* p0 = &Bs[n0 * 32 + ((kgA ^ g) << 2) + t2];
                const float* p1 = &Bs[n0 * 32 + ((kgB ^ g) << 2) + t2];
                float2 v0 = *(const float2*)p0;
                float2 v1 = *(const float2*)p1;
                split_bf(v0.x, v0.y, bh[nt][0], bl[nt][0]);
                split_bf(v1.x, v1.y, bh[nt][1], bl[nt][1]);
            }

#pragma unroll
            for (int mt = 0; mt < 4; mt++) {
                int m0 = wm * 64 + mt * 16 + g;      // m0 & 7 == g, (m0+8) & 7 == g
                uint32_t ah[4], al[4];
                float2 v;
                v = *(const float2*)&As[m0 * 32 + ((kgA ^ g) << 2) + t2];
                split_bf(v.x, v.y, ah[0], al[0]);
                v = *(const float2*)&As[(m0 + 8) * 32 + ((kgA ^ g) << 2) + t2];
                split_bf(v.x, v.y, ah[1], al[1]);
                v = *(const float2*)&As[m0 * 32 + ((kgB ^ g) << 2) + t2];
                split_bf(v.x, v.y, ah[2], al[2]);
                v = *(const float2*)&As[(m0 + 8) * 32 + ((kgB ^ g) << 2) + t2];
                split_bf(v.x, v.y, ah[3], al[3]);

#pragma unroll
                for (int nt = 0; nt < 4; nt++) {
                    mma_bf16(c[mt][nt], ah, bh[nt]);
                    mma_bf16(c[mt][nt], ah, bl[nt]);
                    mma_bf16(c[mt][nt], al, bh[nt]);
                }
            }
        }
    }

    // Epilogue: per-thread partial of sum_h V[h]*tanh(ctx + wq[h])
    float rs[4][2];
#pragma unroll
    for (int mt = 0; mt < 4; mt++) { rs[mt][0] = 0.f; rs[mt][1] = 0.f; }

#pragma unroll
    for (int mt = 0; mt < 4; mt++)
#pragma unroll
        for (int nt = 0; nt < 4; nt++)
#pragma unroll
            for (int j = 0; j < 4; j++) {
                int r = j >> 1, cc = j & 1;
                int hl = wn * 32 + nt * 8 + 2 * t + cc;
                rs[mt][r] = fmaf(vs[hl], tanhf(c[mt][nt][j] + wqs[hl]), rs[mt][r]);
            }

#pragma unroll
    for (int mt = 0; mt < 4; mt++)
#pragma unroll
        for (int r = 0; r < 2; r++) {
            float v = rs[mt][r];
            v += __shfl_xor_sync(0xFFFFFFFF, v, 1);
            v += __shfl_xor_sync(0xFFFFFFFF, v, 2);
            if (t == 0) red[wm * 64 + mt * 16 + r * 8 + g][wn] = v;
        }
    __syncthreads();

    if (tid < 128) {
        float r = (red[tid][0] + red[tid][1]) + (red[tid][2] + red[tid][3]);
        int s = st * 128 + tid;
        g_partial[(size_t)(b * SS + s) * NHT + ht] = r;
    }
}

// ---------------------------------------------------------------------------
// Kernel C: reduce partials -> score (output), softmax -> g_alpha
// ---------------------------------------------------------------------------
__global__ void softmax_kernel(float* __restrict__ out_score) {
    __shared__ float sred[256];
    const int b = blockIdx.x;
    const int tid = threadIdx.x;

    float sc[8];
    float mx = -1e30f;
#pragma unroll
    for (int i = 0; i < 8; i++) {
        int s = i * 256 + tid;
        const float* p = g_partial + (size_t)(b * SS + s) * NHT;
        float v = 0.f;
#pragma unroll
        for (int tt = 0; tt < NHT; tt++) v += p[tt];
        sc[i] = v;
        out_score[b * SS + s] = v;
        mx = fmaxf(mx, v);
    }
    sred[tid] = mx; __syncthreads();
    for (int off = 128; off > 0; off >>= 1) {
        if (tid < off) sred[tid] = fmaxf(sred[tid], sred[tid + off]);
        __syncthreads();
    }
    mx = sred[0]; __syncthreads();

    float ex[8];
    float sum = 0.f;
#pragma unroll
    for (int i = 0; i < 8; i++) { ex[i] = expf(sc[i] - mx); sum += ex[i]; }
    sred[tid] = sum; __syncthreads();
    for (int off = 128; off > 0; off >>= 1) {
        if (tid < off) sred[tid] += sred[tid + off];
        __syncthreads();
    }
    float inv = 1.f / sred[0];
#pragma unroll
    for (int i = 0; i < 8; i++) g_alpha[b * SS + i * 256 + tid] = ex[i] * inv;
}

// ---------------------------------------------------------------------------
// Kernel D: split-K t: tpart[sp][b][e] = sum_{s in slice} enc[b,s,e]*alpha[b,s]
// ---------------------------------------------------------------------------
__global__ void context_t_part(const float* __restrict__ enc) {
    __shared__ float sa[256];
    const int b = blockIdx.y;
    const int sp = blockIdx.z;
    const int tid = threadIdx.x;
    const int s0 = sp * 256;
    sa[tid] = g_alpha[b * SS + s0 + tid];
    __syncthreads();

    const int e = blockIdx.x * 256 + tid;
    const float* p = enc + (size_t)b * SS * EE + (size_t)s0 * EE + e;
    float a0 = 0.f, a1 = 0.f, a2 = 0.f, a3 = 0.f;
#pragma unroll 4
    for (int s = 0; s < 256; s += 4) {
        a0 = fmaf(p[(size_t)(s + 0) * EE], sa[s + 0], a0);
        a1 = fmaf(p[(size_t)(s + 1) * EE], sa[s + 1], a1);
        a2 = fmaf(p[(size_t)(s + 2) * EE], sa[s + 2], a2);
        a3 = fmaf(p[(size_t)(s + 3) * EE], sa[s + 3], a3);
    }
    g_tpart[((size_t)sp * BB + b) * EE + e] = (a0 + a1) + (a2 + a3);
}

__global__ void t_combine() {
    int idx = blockIdx.x * 256 + threadIdx.x;   // BB*EE = 32768
    float v = 0.f;
#pragma unroll
    for (int p = 0; p < 8; p++) v += g_tpart[(size_t)p * BB * EE + idx];
    g_t[idx] = v;
}

// ---------------------------------------------------------------------------
// Kernel E: hidden[b,h] = sum_e Wk[h,e] * t[b,e]
// ---------------------------------------------------------------------------
__global__ void hidden_kernel(const float* __restrict__ Wk,
                              float* __restrict__ out_hidden) {
    int warp = threadIdx.x >> 5;
    int lane = threadIdx.x & 31;
    int h = blockIdx.x * 8 + warp;
    int b = blockIdx.y;
    const float* wrow = Wk + (size_t)h * EE;
    const float* trow = g_t + b * EE;
    float acc = 0.f;
#pragma unroll 8
    for (int e = lane; e < EE; e += 32)
        acc = fmaf(wrow[e], trow[e], acc);
#pragma unroll
    for (int off = 16; off > 0; off >>= 1)
        acc += __shfl_xor_sync(0xFFFFFFFF, acc, off);
    if (lane == 0) out_hidden[b * HH + h] = acc;
}

// ---------------------------------------------------------------------------
extern "C" void kernel_launch(void* const* d_in, const int* in_sizes, int n_in,
                              void* d_out, int out_size) {
    const float* enc = (const float*)d_in[0];   // [B,S,E]
    const float* dec = (const float*)d_in[1];   // [B,E]
    const float* Wk  = (const float*)d_in[2];   // [H,E]
    const float* Wq  = (const float*)d_in[3];   // [H,E]
    const float* V   = (const float*)d_in[4];   // [H]

    float* out_hidden = (float*)d_out;               // [B,H]
    float* out_score  = (float*)d_out + BB * HH;     // [B,S]

    cudaFuncSetAttribute(gemm_tc_kernel, cudaFuncAttributeMaxDynamicSharedMemorySize, DYN_SMEM);

    wq_kernel<<<dim3(HH / 8, BB), 256>>>(dec, Wq);
    gemm_tc_kernel<<<dim3(NHT, SS / 128, BB), 256, DYN_SMEM>>>(enc, Wk, V);
    softmax_kernel<<<BB, 256>>>(out_score);
    context_t_part<<<dim3(EE / 256, BB, 8), 256>>>(enc);
    t_combine<<<BB * EE / 256, 256>>>();
    hidden_kernel<<<dim3(HH / 8, BB), 256>>>(Wk, out_hidden);
}